// round 7
// baseline (speedup 1.0000x reference)
#include <cuda_runtime.h>
#include <cstdint>
#include <math.h>

#define B_ 16
#define S_ 4096
#define DQ_ 1024
#define DM_ 512
#define DO_ 1024
#define H_ 16
#define D_ 64

typedef unsigned long long u64;

// -------- scratch (no allocs allowed) --------
__device__ float g_q[B_ * DO_];          // scaled query projections [b][h*64+d]
__device__ float g_ut[B_ * DM_ * H_];    // folded key proj, TRANSPOSED: [b][m][h]
__device__ float g_c[B_ * H_ * DM_];     // exp-weighted mb sums [b][h][m]
__device__ float g_Z[B_ * H_];           // softmax denominators

// -------- packed fp32x2 helpers --------
__device__ __forceinline__ u64 pack2(float lo, float hi) {
    u64 r; asm("mov.b64 %0, {%1,%2};" : "=l"(r) : "f"(lo), "f"(hi)); return r;
}
__device__ __forceinline__ void unpack2(u64 v, float& lo, float& hi) {
    asm("mov.b64 {%0,%1}, %2;" : "=f"(lo), "=f"(hi) : "l"(v));
}
__device__ __forceinline__ void ffma2(u64& d, u64 a, u64 b) {
    asm("fma.rn.f32x2 %0, %1, %2, %3;" : "=l"(d) : "l"(a), "l"(b), "l"(d));
}

// -------- cp.async helpers --------
__device__ __forceinline__ void cp16(uint32_t dst_smem, const float* src) {
    asm volatile("cp.async.cg.shared.global [%0], [%1], 16;" :: "r"(dst_smem), "l"(src));
}
__device__ __forceinline__ void cp_commit() {
    asm volatile("cp.async.commit_group;");
}
template <int N> __device__ __forceinline__ void cp_wait() {
    asm volatile("cp.async.wait_group %0;" :: "n"(N));
}

// ============================================================
// Kernel 0: zero accumulators (g_q, g_c, g_Z, context slice of out)
// grid 512, block 256
// ============================================================
__global__ __launch_bounds__(256) void k_zero(float* __restrict__ out) {
    int i = blockIdx.x * 256 + threadIdx.x;
    if (i < B_ * DO_) { g_q[i] = 0.f; out[i] = 0.f; }
    if (i < B_ * H_ * DM_) g_c[i] = 0.f;
    if (i < B_ * H_) g_Z[i] = 0.f;
}

// ============================================================
// Kernel 1: q partial, Wq read once. grid (4,16), block 256
// ============================================================
__global__ __launch_bounds__(256) void k_qproj(const float* __restrict__ src,
                                               const float* __restrict__ Wq) {
    __shared__ float s_src[B_][64];
    int t = threadIdx.x;
    int o = blockIdx.x * 256 + t;
    int k0 = blockIdx.y * 64;
#pragma unroll
    for (int i = 0; i < 4; ++i) {
        int idx = i * 256 + t;
        s_src[idx >> 6][idx & 63] = src[(size_t)(idx >> 6) * DQ_ + k0 + (idx & 63)];
    }
    __syncthreads();
    float acc[B_];
#pragma unroll
    for (int b = 0; b < B_; ++b) acc[b] = 0.f;
#pragma unroll 4
    for (int k = 0; k < 64; ++k) {
        float wq = Wq[(size_t)(k0 + k) * DO_ + o];
#pragma unroll
        for (int b = 0; b < B_; ++b) acc[b] = fmaf(s_src[b][k], wq, acc[b]);
    }
#pragma unroll
    for (int b = 0; b < B_; ++b) atomicAdd(&g_q[b * DO_ + o], acc[b] * 0.125f);
}

// ============================================================
// Kernel 2: u[b,h,m] = sum_d Wk[m,h*64+d]*q[b,h,d], stored [b][m][h]
// grid B*H, block 256
// ============================================================
__global__ __launch_bounds__(256) void k_uproj(const float* __restrict__ Wk) {
    int bh = blockIdx.x;
    int b = bh >> 4, h = bh & 15;
    __shared__ float s_q[D_];
    if (threadIdx.x < D_) s_q[threadIdx.x] = g_q[b * DO_ + h * D_ + threadIdx.x];
    __syncthreads();
    for (int m = threadIdx.x; m < DM_; m += 256) {
        const float4* w = reinterpret_cast<const float4*>(Wk + (size_t)m * DO_ + h * D_);
        float acc = 0.f;
#pragma unroll
        for (int d4 = 0; d4 < D_ / 4; ++d4) {
            float4 wv = w[d4];
            acc = fmaf(wv.x, s_q[d4 * 4 + 0], acc);
            acc = fmaf(wv.y, s_q[d4 * 4 + 1], acc);
            acc = fmaf(wv.z, s_q[d4 * 4 + 2], acc);
            acc = fmaf(wv.w, s_q[d4 * 4 + 3], acc);
        }
        g_ut[((size_t)b * DM_ + m) * H_ + h] = acc;
    }
}

// ============================================================
// Kernel 3: e[b,h,s] = exp(score) (masked -> 0), Z accumulated.
// cp.async double-buffered mb staging. grid (32, B), block 128.
// Dynamic smem: u_s[512*16] | mb_s[2][128*36] | s_Z[16]
// ============================================================
#define TS3 128
#define KC3 32
#define P3 36
#define NCH3 (DM_ / KC3)
__global__ __launch_bounds__(128) void k_scores(const float* __restrict__ mb,
                                                float* __restrict__ attn,
                                                const int* __restrict__ mask) {
    extern __shared__ __align__(16) float sm[];
    float* u_s = sm;                       // 8192 floats
    float* mb_sh = sm + DM_ * H_;          // 2 * 128*36 floats
    float* s_Z = mb_sh + 2 * TS3 * P3;     // 16 floats

    int b = blockIdx.y, s_tile = blockIdx.x * TS3;
    int t = threadIdx.x, w = t >> 5, l = t & 31;
    int sb = w * 32 + (l & 7);             // s base; owns sb, sb+8, sb+16, sb+24
    int h0 = (l >> 3) * 4;

    const float* mb_b = mb + ((size_t)b * S_ + s_tile) * DM_;
    const float* u_b = g_ut + (size_t)b * DM_ * H_;

    // stage u fully (coalesced float4)
#pragma unroll
    for (int i = 0; i < 16; ++i) {
        int idx = i * 128 + t;
        reinterpret_cast<float4*>(u_s)[idx] = reinterpret_cast<const float4*>(u_b)[idx];
    }
    if (t < H_) s_Z[t] = 0.f;

    uint32_t mb_base = (uint32_t)__cvta_generic_to_shared(mb_sh);

    // stage chunk kc into buffer buf
    auto stage = [&](int kc, int buf) {
        uint32_t dst0 = mb_base + (uint32_t)buf * (TS3 * P3 * 4);
#pragma unroll
        for (int i = 0; i < 8; ++i) {
            int idx = i * 128 + t;
            int row = idx >> 3, f4 = idx & 7;
            cp16(dst0 + (uint32_t)(row * (P3 * 4) + f4 * 16),
                 mb_b + (size_t)row * DM_ + kc * KC3 + f4 * 4);
        }
        cp_commit();
    };

    u64 acc[2][4];
#pragma unroll
    for (int i = 0; i < 2; ++i)
#pragma unroll
        for (int j = 0; j < 4; ++j) acc[i][j] = 0ull;

    stage(0, 0);
    for (int kc = 0; kc < NCH3; ++kc) {
        if (kc + 1 < NCH3) { stage(kc + 1, (kc + 1) & 1); cp_wait<1>(); }
        else cp_wait<0>();
        __syncthreads();
        const float* mbuf = mb_sh + (kc & 1) * (TS3 * P3);
#pragma unroll
        for (int k = 0; k < KC3; ++k) {
            ulonglong2 up = *reinterpret_cast<const ulonglong2*>(
                &u_s[(kc * KC3 + k) * H_ + h0]);
            float m0 = mbuf[(sb +  0) * P3 + k];
            float m1 = mbuf[(sb +  8) * P3 + k];
            float m2 = mbuf[(sb + 16) * P3 + k];
            float m3 = mbuf[(sb + 24) * P3 + k];
            u64 d0 = pack2(m0, m0), d1 = pack2(m1, m1);
            u64 d2 = pack2(m2, m2), d3 = pack2(m3, m3);
            ffma2(acc[0][0], up.x, d0); ffma2(acc[1][0], up.y, d0);
            ffma2(acc[0][1], up.x, d1); ffma2(acc[1][1], up.y, d1);
            ffma2(acc[0][2], up.x, d2); ffma2(acc[1][2], up.y, d2);
            ffma2(acc[0][3], up.x, d3); ffma2(acc[1][3], up.y, d3);
        }
        __syncthreads();
    }

    // epilogue: mask -> exp -> store e, accumulate Z
    float zp[4] = {0.f, 0.f, 0.f, 0.f};
#pragma unroll
    for (int j = 0; j < 4; ++j) {
        int s = s_tile + sb + j * 8;
        bool msk = (mask[(size_t)b * S_ + s] != 0);
#pragma unroll
        for (int hp = 0; hp < 2; ++hp) {
            float lo, hi;
            unpack2(acc[hp][j], lo, hi);
            float e0 = msk ? 0.f : expf(lo);
            float e1 = msk ? 0.f : expf(hi);
            attn[(size_t)(b * H_ + h0 + hp * 2 + 0) * S_ + s] = e0;
            attn[(size_t)(b * H_ + h0 + hp * 2 + 1) * S_ + s] = e1;
            zp[hp * 2 + 0] += e0;
            zp[hp * 2 + 1] += e1;
        }
    }
    atomicAdd(&s_Z[h0 + 0], zp[0]);
    atomicAdd(&s_Z[h0 + 1], zp[1]);
    atomicAdd(&s_Z[h0 + 2], zp[2]);
    atomicAdd(&s_Z[h0 + 3], zp[3]);
    __syncthreads();
    if (t < H_) atomicAdd(&g_Z[b * H_ + t], s_Z[t]);
}

// ============================================================
// Kernel 4: normalize attn rows by Z. grid B*H, block 256
// ============================================================
__global__ __launch_bounds__(256) void k_norm(float* __restrict__ attn) {
    int bh = blockIdx.x;
    float inv = 1.f / g_Z[bh];
    float4* row = reinterpret_cast<float4*>(attn + (size_t)bh * S_);
#pragma unroll
    for (int i = 0; i < 4; ++i) {
        float4 v = row[threadIdx.x + i * 256];
        v.x *= inv; v.y *= inv; v.z *= inv; v.w *= inv;
        row[threadIdx.x + i * 256] = v;
    }
}

// ============================================================
// Kernel 5: c[b,h,m] += sum_s attn[b,h,s]*mb[b,s,m]
// cp.async double-buffered. grid (4, 16, B), block 128.
// Dynamic smem: mb_s[2][32*132] | a_s[256*17]
// ============================================================
#define SC5 32
#define MT5 128
#define P5 132
__global__ __launch_bounds__(128) void k_ctxacc(const float* __restrict__ mb,
                                                const float* __restrict__ attn) {
    extern __shared__ __align__(16) float sm5[];
    float* mb_sh = sm5;                      // 2 * 32*132
    float* a_s = sm5 + 2 * SC5 * P5;         // 256*17

    int m_base = blockIdx.x * MT5;
    int s_base = blockIdx.y * 256;
    int b = blockIdx.z;
    int t = threadIdx.x, w = t >> 5, l = t & 31;
    int m_loc = w * 32 + (l & 7) * 4;
    int h0 = (l >> 3) * 4;

    const float* mb_b = mb + ((size_t)b * S_ + s_base) * DM_ + m_base;
    const float* a_b = attn + (size_t)b * H_ * S_ + s_base;

    // stage all attn for this s-range: 256 s x 16 h
#pragma unroll
    for (int i = 0; i < 32; ++i) {
        int idx = i * 128 + t;
        int h = idx >> 8, s = idx & 255;
        a_s[s * 17 + h] = a_b[(size_t)h * S_ + s];
    }

    uint32_t mb_base = (uint32_t)__cvta_generic_to_shared(mb_sh);
    auto stage = [&](int ch, int buf) {
        uint32_t dst0 = mb_base + (uint32_t)buf * (SC5 * P5 * 4);
#pragma unroll
        for (int i = 0; i < 8; ++i) {
            int idx = i * 128 + t;
            int row = idx >> 5, f4 = idx & 31;
            cp16(dst0 + (uint32_t)(row * (P5 * 4) + f4 * 16),
                 mb_b + (size_t)(ch * 32 + row) * DM_ + f4 * 4);
        }
        cp_commit();
    };

    u64 acc[4][2];
#pragma unroll
    for (int i = 0; i < 4; ++i)
#pragma unroll
        for (int j = 0; j < 2; ++j) acc[i][j] = 0ull;

    stage(0, 0);
    for (int ch = 0; ch < 8; ++ch) {
        if (ch + 1 < 8) { stage(ch + 1, (ch + 1) & 1); cp_wait<1>(); }
        else cp_wait<0>();
        __syncthreads();
        const float* mbuf = mb_sh + (ch & 1) * (SC5 * P5);
#pragma unroll
        for (int k = 0; k < SC5; ++k) {
            ulonglong2 mp = *reinterpret_cast<const ulonglong2*>(&mbuf[k * P5 + m_loc]);
            int sl = ch * 32 + k;
            float a0 = a_s[sl * 17 + h0 + 0];
            float a1 = a_s[sl * 17 + h0 + 1];
            float a2 = a_s[sl * 17 + h0 + 2];
            float a3 = a_s[sl * 17 + h0 + 3];
            u64 d0 = pack2(a0, a0), d1 = pack2(a1, a1);
            u64 d2 = pack2(a2, a2), d3 = pack2(a3, a3);
            ffma2(acc[0][0], mp.x, d0); ffma2(acc[0][1], mp.y, d0);
            ffma2(acc[1][0], mp.x, d1); ffma2(acc[1][1], mp.y, d1);
            ffma2(acc[2][0], mp.x, d2); ffma2(acc[2][1], mp.y, d2);
            ffma2(acc[3][0], mp.x, d3); ffma2(acc[3][1], mp.y, d3);
        }
        __syncthreads();
    }
#pragma unroll
    for (int j = 0; j < 4; ++j) {
        float x0, x1, x2, x3;
        unpack2(acc[j][0], x0, x1);
        unpack2(acc[j][1], x2, x3);
        float* dst = g_c + (size_t)(b * H_ + h0 + j) * DM_ + m_base + m_loc;
        atomicAdd(dst + 0, x0);
        atomicAdd(dst + 1, x1);
        atomicAdd(dst + 2, x2);
        atomicAdd(dst + 3, x3);
    }
}

// ============================================================
// Kernel 6: context[b,h*64+d] += sum_m c[b,h,m]*Wv[m,h*64+d]
// Wv staged once, reused by all b. grid (H, 8), block 256
// ============================================================
__global__ __launch_bounds__(256) void k_ctx(const float* __restrict__ Wv,
                                             float* __restrict__ out) {
    __shared__ float wv_s[64][65];
    __shared__ float c_s[B_][64];
    int h = blockIdx.x;
    int m0 = blockIdx.y * 64;
    int t = threadIdx.x;
#pragma unroll
    for (int i = 0; i < 16; ++i) {
        int idx = i * 256 + t;
        wv_s[idx >> 6][idx & 63] = Wv[(size_t)(m0 + (idx >> 6)) * DO_ + h * D_ + (idx & 63)];
    }
#pragma unroll
    for (int i = 0; i < 4; ++i) {
        int idx = i * 256 + t;
        c_s[idx >> 6][idx & 63] = g_c[(size_t)((idx >> 6) * H_ + h) * DM_ + m0 + (idx & 63)];
    }
    __syncthreads();
    int d = t & 63, bg = t >> 6;
    float acc[4] = {0.f, 0.f, 0.f, 0.f};
#pragma unroll 8
    for (int mm = 0; mm < 64; ++mm) {
        float wv = wv_s[mm][d];
#pragma unroll
        for (int j = 0; j < 4; ++j) acc[j] = fmaf(c_s[bg + j * 4][mm], wv, acc[j]);
    }
#pragma unroll
    for (int j = 0; j < 4; ++j)
        atomicAdd(&out[(size_t)(bg + j * 4) * DO_ + h * D_ + d], acc[j]);
}

// ============================================================
extern "C" void kernel_launch(void* const* d_in, const int* in_sizes, int n_in,
                              void* d_out, int out_size) {
    const float* src = (const float*)d_in[0];
    const float* mb = (const float*)d_in[1];
    const float* Wq = (const float*)d_in[2];
    const float* Wk = (const float*)d_in[3];
    const float* Wv = (const float*)d_in[4];
    const int* mask = (const int*)d_in[5];
    float* out = (float*)d_out;
    float* attn = out + B_ * DO_;  // context first, then attn [B,H,S]

    const int SM3 = (DM_ * H_ + 2 * TS3 * P3 + 16) * sizeof(float);   // 69760 B
    const int SM5 = (2 * SC5 * P5 + 256 * 17) * sizeof(float);        // 51200 B
    static bool attr_done = false;
    if (!attr_done) {
        cudaFuncSetAttribute(k_scores, cudaFuncAttributeMaxDynamicSharedMemorySize, SM3);
        cudaFuncSetAttribute(k_ctxacc, cudaFuncAttributeMaxDynamicSharedMemorySize, SM5);
        attr_done = true;
    }

    k_zero<<<512, 256>>>(out);
    k_qproj<<<dim3(DO_ / 256, DQ_ / 64), 256>>>(src, Wq);
    k_uproj<<<B_ * H_, 256>>>(Wk);
    k_scores<<<dim3(S_ / TS3, B_), 128, SM3>>>(mb, attn, mask);
    k_norm<<<B_ * H_, 256>>>(attn);
    k_ctxacc<<<dim3(DM_ / MT5, S_ / 256, B_), 128, SM5>>>(mb, attn);
    k_ctx<<<dim3(H_, DM_ / 64), 256>>>(Wv, out);
}